// round 1
// baseline (speedup 1.0000x reference)
#include <cuda_runtime.h>
#include <math.h>
#include <float.h>

#define BB 64
#define SS 2048
#define ED 1024
#define AD 512

// Scratch (allocation-free rule: __device__ globals)
__device__ float g_dec_feat[BB * AD];   // [B, AD]
__device__ float g_scores[BB * SS];     // [B, S]
__device__ int   g_mask_mode;           // 0=int32, 1=float32, 2=uint8

// ---------------------------------------------------------------------------
// Kernel 1: dec_feat[b][a] = dot(decoder_hidden[b], W_dec[a])
// grid (B, AD/8), block 256 (8 warps, one warp per 'a')
// ---------------------------------------------------------------------------
__global__ void decfeat_kernel(const float* __restrict__ dh,
                               const float* __restrict__ Wdec) {
    int b = blockIdx.x;
    __shared__ float s_dh[ED];
    for (int i = threadIdx.x; i < ED; i += 256) s_dh[i] = dh[b * ED + i];
    __syncthreads();

    int warp = threadIdx.x >> 5;
    int lane = threadIdx.x & 31;
    int a = blockIdx.y * 8 + warp;
    const float* wr = Wdec + (size_t)a * ED;
    float acc = 0.f;
    #pragma unroll 8
    for (int k = lane; k < ED; k += 32) acc += s_dh[k] * wr[k];
    #pragma unroll
    for (int off = 16; off; off >>= 1) acc += __shfl_down_sync(0xffffffffu, acc, off);
    if (lane == 0) g_dec_feat[b * AD + a] = acc;
}

// ---------------------------------------------------------------------------
// Kernel 2: fused  scores[b,s] = sum_a We[a] * tanh( X[b,s,:]·Wenc[a,:] + dec[b,a] )
// Tiled GEMM: 128 rows x 128 att-cols per block, K=1024 swept per a-chunk.
// 256 threads, 8x8 register micro-tile.
// ---------------------------------------------------------------------------
#define TS 128
#define TA 128
#define KC 16
#define XPAD 132   // row stride (floats), multiple of 4 for aligned float4 LDS

__global__ void __launch_bounds__(256, 2)
score_kernel(const float* __restrict__ X,      // [B*S, ED]
             const float* __restrict__ Wenc,   // [AD, ED]
             const float* __restrict__ Wen,    // [AD]
             float* __restrict__ scores) {
    int b  = blockIdx.x;
    int s0 = blockIdx.y * TS;

    __shared__ float Xs[KC][XPAD];
    __shared__ float Ws[KC][XPAD];
    __shared__ float s_dec[TA];
    __shared__ float s_we[TA];

    int tid = threadIdx.x;
    int tx = tid & 15;        // 16 col groups
    int ty = tid >> 4;        // 16 row groups

    const float* Xblk = X + (size_t)(b * SS + s0) * ED;

    float rs[8];
    #pragma unroll
    for (int i = 0; i < 8; ++i) rs[i] = 0.f;

    for (int ac = 0; ac < AD / TA; ++ac) {
        int a0 = ac * TA;
        __syncthreads();   // protect s_dec/s_we from previous chunk's readers
        if (tid < TA) {
            s_dec[tid] = g_dec_feat[b * AD + a0 + tid];
            s_we[tid]  = Wen[a0 + tid];
        }

        float acc[8][8];
        #pragma unroll
        for (int i = 0; i < 8; ++i)
            #pragma unroll
            for (int j = 0; j < 8; ++j) acc[i][j] = 0.f;

        for (int k0 = 0; k0 < ED; k0 += KC) {
            __syncthreads();
            // Load X tile (transposed into smem) and W tile: 512 float4 each
            #pragma unroll
            for (int l = 0; l < 2; ++l) {
                int idx = tid + l * 256;         // 0..511
                int row = idx >> 2;              // 0..127
                int kq  = (idx & 3) * 4;         // 0,4,8,12
                float4 v = *(const float4*)(Xblk + (size_t)row * ED + k0 + kq);
                Xs[kq + 0][row] = v.x; Xs[kq + 1][row] = v.y;
                Xs[kq + 2][row] = v.z; Xs[kq + 3][row] = v.w;
                float4 w = *(const float4*)(Wenc + (size_t)(a0 + row) * ED + k0 + kq);
                Ws[kq + 0][row] = w.x; Ws[kq + 1][row] = w.y;
                Ws[kq + 2][row] = w.z; Ws[kq + 3][row] = w.w;
            }
            __syncthreads();

            #pragma unroll
            for (int k = 0; k < KC; ++k) {
                float4 x0 = *(const float4*)&Xs[k][ty * 8];
                float4 x1 = *(const float4*)&Xs[k][ty * 8 + 4];
                float4 w0 = *(const float4*)&Ws[k][tx * 8];
                float4 w1 = *(const float4*)&Ws[k][tx * 8 + 4];
                float xr[8] = {x0.x, x0.y, x0.z, x0.w, x1.x, x1.y, x1.z, x1.w};
                float wr[8] = {w0.x, w0.y, w0.z, w0.w, w1.x, w1.y, w1.z, w1.w};
                #pragma unroll
                for (int i = 0; i < 8; ++i)
                    #pragma unroll
                    for (int j = 0; j < 8; ++j)
                        acc[i][j] += xr[i] * wr[j];
            }
        }

        // epilogue: tanh + energy reduction over this a-chunk
        #pragma unroll
        for (int i = 0; i < 8; ++i) {
            float p = 0.f;
            #pragma unroll
            for (int j = 0; j < 8; ++j) {
                int a = tx * 8 + j;
                p += s_we[a] * tanhf(acc[i][j] + s_dec[a]);
            }
            rs[i] += p;
        }
    }

    // reduce rs across the 16 tx lanes (two independent 16-lane halves per warp)
    #pragma unroll
    for (int i = 0; i < 8; ++i) {
        float v = rs[i];
        v += __shfl_down_sync(0xffffffffu, v, 8);
        v += __shfl_down_sync(0xffffffffu, v, 4);
        v += __shfl_down_sync(0xffffffffu, v, 2);
        v += __shfl_down_sync(0xffffffffu, v, 1);
        if (tx == 0) scores[b * SS + s0 + ty * 8 + i] = v;
    }
}

// ---------------------------------------------------------------------------
// Kernel 3: detect mask dtype from bit patterns. Single block.
//  int32 mask: every 32-bit word is 0 or 1.
//  float32 mask: every word is 0 or 0x3F800000.
//  uint8 mask: packed 0/1 bytes -> words like 0x00010001 appear.
// Scans 32768 words = min buffer size across the three interpretations.
// ---------------------------------------------------------------------------
__global__ void mask_detect_kernel(const unsigned int* __restrict__ mw) {
    __shared__ int s_not01, s_notf;
    if (threadIdx.x == 0) { s_not01 = 0; s_notf = 0; }
    __syncthreads();
    int not01 = 0, notf = 0;
    for (int i = threadIdx.x; i < 32768; i += blockDim.x) {
        unsigned int w = mw[i];
        if (w > 1u) not01 = 1;
        if (w != 0u && w != 0x3F800000u) notf = 1;
    }
    if (not01) atomicOr(&s_not01, 1);
    if (notf)  atomicOr(&s_notf, 1);
    __syncthreads();
    if (threadIdx.x == 0)
        g_mask_mode = (!s_not01) ? 0 : (!s_notf ? 1 : 2);
}

// ---------------------------------------------------------------------------
// Kernel 4: masked softmax over S per batch row. grid B, block 256.
// mask==True -> score = -FLT_MAX (matches jnp.where(mask, finfo.min, scores))
// ---------------------------------------------------------------------------
__global__ void softmax_kernel(const float* __restrict__ scores,
                               const void* __restrict__ mask,
                               float* __restrict__ wout) {
    int b = blockIdx.x;
    int tid = threadIdx.x;
    int mode = g_mask_mode;
    __shared__ float red[256];

    float sv[8];
    float mx = -FLT_MAX;
    #pragma unroll
    for (int i = 0; i < 8; ++i) {
        int s = tid + i * 256;
        float v = scores[b * SS + s];
        bool m;
        if (mode == 0)      m = ((const int*)mask)[b * SS + s] != 0;
        else if (mode == 1) m = ((const float*)mask)[b * SS + s] != 0.f;
        else                m = ((const unsigned char*)mask)[b * SS + s] != 0;
        v = m ? -FLT_MAX : v;
        sv[i] = v;
        mx = fmaxf(mx, v);
    }
    red[tid] = mx; __syncthreads();
    for (int off = 128; off; off >>= 1) {
        if (tid < off) red[tid] = fmaxf(red[tid], red[tid + off]);
        __syncthreads();
    }
    mx = red[0];
    __syncthreads();

    float sum = 0.f;
    #pragma unroll
    for (int i = 0; i < 8; ++i) {
        float e = expf(sv[i] - mx);
        sv[i] = e;
        sum += e;
    }
    red[tid] = sum; __syncthreads();
    for (int off = 128; off; off >>= 1) {
        if (tid < off) red[tid] += red[tid + off];
        __syncthreads();
    }
    float inv = 1.f / red[0];
    #pragma unroll
    for (int i = 0; i < 8; ++i)
        wout[b * SS + tid + i * 256] = sv[i] * inv;
}

// ---------------------------------------------------------------------------
// Kernel 5: context[b,e] = sum_s w[b,s] * enc[b,s,e]
// grid (B, ED/256), block 256, one e per thread; streaming read of enc.
// ---------------------------------------------------------------------------
__global__ void context_kernel(const float* __restrict__ enc,
                               const float* __restrict__ w,
                               float* __restrict__ out) {
    int b = blockIdx.x;
    int e = blockIdx.y * 256 + threadIdx.x;
    const float* ep = enc + (size_t)b * SS * ED + e;
    const float* wp = w + b * SS;
    float acc = 0.f;
    for (int s = 0; s < SS; s += 16) {
        #pragma unroll
        for (int u = 0; u < 16; ++u)
            acc += wp[s + u] * ep[(size_t)(s + u) * ED];
    }
    out[(size_t)b * ED + e] = acc;
}

// ---------------------------------------------------------------------------
extern "C" void kernel_launch(void* const* d_in, const int* in_sizes, int n_in,
                              void* d_out, int out_size) {
    const float* decoder_hidden  = (const float*)d_in[0];  // [64,1024]
    const float* encoder_outputs = (const float*)d_in[1];  // [64,2048,1024]
    const void*  mask            = d_in[2];                // [64,2048] dtype detected
    const float* W_enc           = (const float*)d_in[3];  // [512,1024]
    const float* W_dec           = (const float*)d_in[4];  // [512,1024]
    const float* W_energy        = (const float*)d_in[5];  // [1,512]

    float* out_context = (float*)d_out;                    // [64,1024]
    float* out_weights = (float*)d_out + (size_t)BB * ED;  // [64,2048]

    float* dscores;
    cudaGetSymbolAddress((void**)&dscores, g_scores);

    decfeat_kernel<<<dim3(BB, AD / 8), 256>>>(decoder_hidden, W_dec);
    score_kernel<<<dim3(BB, SS / TS), 256>>>(encoder_outputs, W_enc, W_energy, dscores);
    mask_detect_kernel<<<1, 256>>>((const unsigned int*)mask);
    softmax_kernel<<<BB, 256>>>(dscores, mask, out_weights);
    context_kernel<<<dim3(BB, ED / 256), 256>>>(encoder_outputs, out_weights, out_context);
}

// round 5
// speedup vs baseline: 2.7037x; 2.7037x over previous
#include <cuda_runtime.h>
#include <math.h>
#include <float.h>
#include <stdint.h>

#define BB 64
#define SS 2048
#define ED 1024
#define AD 512

// Scratch (allocation-free rule: __device__ globals)
__device__ float g_dec_feat[BB * AD];       // [B, AD]
__device__ float g_part[4 * BB * SS];       // [nc][B, S] score partials
__device__ int   g_mask_mode;               // 0=int32, 1=float32, 2=uint8

__device__ __forceinline__ uint32_t smem_u32(const void* p) {
    uint32_t a;
    asm("{ .reg .u64 t; cvta.to.shared.u64 t, %1; cvt.u32.u64 %0, t; }"
        : "=r"(a) : "l"(p));
    return a;
}
__device__ __forceinline__ uint32_t f2tf32(float x) {
    uint32_t r;
    asm("cvt.rna.tf32.f32 %0, %1;" : "=r"(r) : "f"(x));
    return r;
}

// ---------------------------------------------------------------------------
// Kernel 1: dec_feat[b][a] = dot(decoder_hidden[b], W_dec[a])
// ---------------------------------------------------------------------------
__global__ void decfeat_kernel(const float* __restrict__ dh,
                               const float* __restrict__ Wdec) {
    int b = blockIdx.x;
    __shared__ float s_dh[ED];
    for (int i = threadIdx.x; i < ED; i += 256) s_dh[i] = dh[b * ED + i];
    __syncthreads();
    int warp = threadIdx.x >> 5;
    int lane = threadIdx.x & 31;
    int a = blockIdx.y * 8 + warp;
    const float* wr = Wdec + (size_t)a * ED;
    float acc = 0.f;
    #pragma unroll 8
    for (int k = lane; k < ED; k += 32) acc += s_dh[k] * wr[k];
    #pragma unroll
    for (int off = 16; off; off >>= 1) acc += __shfl_down_sync(0xffffffffu, acc, off);
    if (lane == 0) g_dec_feat[b * AD + a] = acc;
}

// ---------------------------------------------------------------------------
// Kernel 2: tf32 mma.sync fused score kernel.
// Per CTA: 128 s-rows x 128 a-cols, K=1024, BK=32, 4-stage cp.async pipeline.
// partial[nc][b,s] = sum_{a in chunk} We[a] * tanh(X.Wenc^T + dec)
// ---------------------------------------------------------------------------
#define BK 32
#define NK (ED / BK)          // 32
#define NSTAGE 4
#define RS 36                 // smem row stride in floats (36 % 32 == 4)
#define STAGE_FLOATS (256 * RS)   // X 128 rows + W 128 rows

__global__ void __launch_bounds__(256, 1)
score_mma_kernel(const float* __restrict__ X,     // [B*S, ED]
                 const float* __restrict__ Wenc,  // [AD, ED]
                 const float* __restrict__ Wen)   // [AD]
{
    extern __shared__ float smem[];
    __shared__ float s_dec[128];
    __shared__ float s_we[128];
    __shared__ float s_red[2][128];

    int tid  = threadIdx.x;
    int wid  = tid >> 5;
    int lane = tid & 31;
    int g    = lane >> 2;
    int tig  = lane & 3;
    int warpm = wid & 3;       // 0..3
    int warpn = wid >> 2;      // 0..1

    int nc = blockIdx.x & 3;
    int b  = blockIdx.x >> 2;
    int s0 = blockIdx.y * 128;

    const float* Xblk = X + (size_t)(b * SS + s0) * ED;
    const float* Wblk = Wenc + (size_t)(nc * 128) * ED;

    for (int i = tid; i < 128; i += 256) {
        s_dec[i] = g_dec_feat[b * AD + nc * 128 + i];
        s_we[i]  = Wen[nc * 128 + i];
    }

    uint32_t sm0 = smem_u32(smem);

    // issue one stage's cp.asyncs: slot p, k-chunk kc
    auto issue_stage = [&](int p, int kc) {
        uint32_t base = sm0 + (uint32_t)(p * STAGE_FLOATS) * 4u;
        int k0 = kc * BK;
        #pragma unroll
        for (int i = 0; i < 8; ++i) {
            int c = tid + i * 256;        // 0..2047
            int row = (c >> 3) & 127;
            int q = c & 7;
            const float* src;
            uint32_t dst;
            if (c < 1024) {
                src = Xblk + (size_t)row * ED + k0 + q * 4;
                dst = base + (uint32_t)(row * RS + q * 4) * 4u;
            } else {
                src = Wblk + (size_t)row * ED + k0 + q * 4;
                dst = base + (uint32_t)((128 + row) * RS + q * 4) * 4u;
            }
            asm volatile("cp.async.cg.shared.global [%0], [%1], 16;"
                         :: "r"(dst), "l"(src));
        }
        asm volatile("cp.async.commit_group;" ::: "memory");
    };

    // prologue: stages 0..NSTAGE-2
    issue_stage(0, 0);
    issue_stage(1, 1);
    issue_stage(2, 2);

    float acc[2][8][4];
    #pragma unroll
    for (int mf = 0; mf < 2; ++mf)
        #pragma unroll
        for (int nf = 0; nf < 8; ++nf)
            #pragma unroll
            for (int r = 0; r < 4; ++r) acc[mf][nf][r] = 0.f;

    for (int kt = 0; kt < NK; ++kt) {
        int p = kt & (NSTAGE - 1);
        asm volatile("cp.async.wait_group %0;" :: "n"(NSTAGE - 2) : "memory");
        __syncthreads();

        const float* xs = smem + p * STAGE_FLOATS;
        const float* ws = xs + 128 * RS;

        #pragma unroll
        for (int ks = 0; ks < 4; ++ks) {
            int kb = ks * 8 + tig;
            uint32_t A[2][4];
            #pragma unroll
            for (int mf = 0; mf < 2; ++mf) {
                int r = warpm * 32 + mf * 16 + g;
                const float* xr = xs + r * RS + kb;
                A[mf][0] = f2tf32(xr[0]);
                A[mf][1] = f2tf32(xr[8 * RS]);
                A[mf][2] = f2tf32(xr[4]);
                A[mf][3] = f2tf32(xr[8 * RS + 4]);
            }
            uint32_t Bf[8][2];
            #pragma unroll
            for (int nf = 0; nf < 8; ++nf) {
                int n = warpn * 64 + nf * 8 + g;
                const float* wr = ws + n * RS + kb;
                Bf[nf][0] = f2tf32(wr[0]);
                Bf[nf][1] = f2tf32(wr[4]);
            }
            #pragma unroll
            for (int mf = 0; mf < 2; ++mf)
                #pragma unroll
                for (int nf = 0; nf < 8; ++nf) {
                    float* c = acc[mf][nf];
                    asm volatile(
                        "mma.sync.aligned.m16n8k8.row.col.f32.tf32.tf32.f32 "
                        "{%0,%1,%2,%3}, {%4,%5,%6,%7}, {%8,%9}, {%0,%1,%2,%3};"
                        : "+f"(c[0]), "+f"(c[1]), "+f"(c[2]), "+f"(c[3])
                        : "r"(A[mf][0]), "r"(A[mf][1]), "r"(A[mf][2]), "r"(A[mf][3]),
                          "r"(Bf[nf][0]), "r"(Bf[nf][1]));
                }
        }
        __syncthreads();
        if (kt + NSTAGE - 1 < NK)
            issue_stage((kt + NSTAGE - 1) & (NSTAGE - 1), kt + NSTAGE - 1);
    }

    // ---- epilogue: tanh + We reduction ----
    #pragma unroll
    for (int mf = 0; mf < 2; ++mf) {
        float sum0 = 0.f, sum1 = 0.f;
        #pragma unroll
        for (int nf = 0; nf < 8; ++nf) {
            int cA = warpn * 64 + nf * 8 + 2 * tig;
            int cB = cA + 1;
            sum0 += s_we[cA] * tanhf(acc[mf][nf][0] + s_dec[cA])
                  + s_we[cB] * tanhf(acc[mf][nf][1] + s_dec[cB]);
            sum1 += s_we[cA] * tanhf(acc[mf][nf][2] + s_dec[cA])
                  + s_we[cB] * tanhf(acc[mf][nf][3] + s_dec[cB]);
        }
        sum0 += __shfl_xor_sync(0xffffffffu, sum0, 1);
        sum0 += __shfl_xor_sync(0xffffffffu, sum0, 2);
        sum1 += __shfl_xor_sync(0xffffffffu, sum1, 1);
        sum1 += __shfl_xor_sync(0xffffffffu, sum1, 2);
        if (tig == 0) {
            int r0 = warpm * 32 + mf * 16 + g;
            s_red[warpn][r0]     = sum0;
            s_red[warpn][r0 + 8] = sum1;
        }
    }
    __syncthreads();
    if (tid < 128)
        g_part[nc * BB * SS + b * SS + s0 + tid] = s_red[0][tid] + s_red[1][tid];
}

// ---------------------------------------------------------------------------
// Kernel 3: mask dtype detect
// ---------------------------------------------------------------------------
__global__ void mask_detect_kernel(const unsigned int* __restrict__ mw) {
    __shared__ int s_not01, s_notf;
    if (threadIdx.x == 0) { s_not01 = 0; s_notf = 0; }
    __syncthreads();
    int not01 = 0, notf = 0;
    for (int i = threadIdx.x; i < 32768; i += blockDim.x) {
        unsigned int w = mw[i];
        if (w > 1u) not01 = 1;
        if (w != 0u && w != 0x3F800000u) notf = 1;
    }
    if (not01) atomicOr(&s_not01, 1);
    if (notf)  atomicOr(&s_notf, 1);
    __syncthreads();
    if (threadIdx.x == 0)
        g_mask_mode = (!s_not01) ? 0 : (!s_notf ? 1 : 2);
}

// ---------------------------------------------------------------------------
// Kernel 4: masked softmax (sums the 4 score partials)
// ---------------------------------------------------------------------------
__global__ void softmax_kernel(const void* __restrict__ mask,
                               float* __restrict__ wout) {
    int b = blockIdx.x;
    int tid = threadIdx.x;
    int mode = g_mask_mode;
    __shared__ float red[256];

    float sv[8];
    float mx = -FLT_MAX;
    #pragma unroll
    for (int i = 0; i < 8; ++i) {
        int s = tid + i * 256;
        int idx = b * SS + s;
        float v = g_part[idx] + g_part[BB * SS + idx]
                + g_part[2 * BB * SS + idx] + g_part[3 * BB * SS + idx];
        bool m;
        if (mode == 0)      m = ((const int*)mask)[idx] != 0;
        else if (mode == 1) m = ((const float*)mask)[idx] != 0.f;
        else                m = ((const unsigned char*)mask)[idx] != 0;
        v = m ? -FLT_MAX : v;
        sv[i] = v;
        mx = fmaxf(mx, v);
    }
    red[tid] = mx; __syncthreads();
    for (int off = 128; off; off >>= 1) {
        if (tid < off) red[tid] = fmaxf(red[tid], red[tid + off]);
        __syncthreads();
    }
    mx = red[0];
    __syncthreads();

    float sum = 0.f;
    #pragma unroll
    for (int i = 0; i < 8; ++i) {
        float e = expf(sv[i] - mx);
        sv[i] = e;
        sum += e;
    }
    red[tid] = sum; __syncthreads();
    for (int off = 128; off; off >>= 1) {
        if (tid < off) red[tid] += red[tid + off];
        __syncthreads();
    }
    float inv = 1.f / red[0];
    #pragma unroll
    for (int i = 0; i < 8; ++i)
        wout[b * SS + tid + i * 256] = sv[i] * inv;
}

// ---------------------------------------------------------------------------
// Kernel 5: context[b,e] = sum_s w[b,s] * enc[b,s,e]
// ---------------------------------------------------------------------------
__global__ void context_kernel(const float* __restrict__ enc,
                               const float* __restrict__ w,
                               float* __restrict__ out) {
    int b = blockIdx.x;
    int e = blockIdx.y * 256 + threadIdx.x;
    const float* ep = enc + (size_t)b * SS * ED + e;
    const float* wp = w + b * SS;
    float acc = 0.f;
    for (int s = 0; s < SS; s += 16) {
        #pragma unroll
        for (int u = 0; u < 16; ++u)
            acc += wp[s + u] * ep[(size_t)(s + u) * ED];
    }
    out[(size_t)b * ED + e] = acc;
}

// ---------------------------------------------------------------------------
extern "C" void kernel_launch(void* const* d_in, const int* in_sizes, int n_in,
                              void* d_out, int out_size) {
    const float* decoder_hidden  = (const float*)d_in[0];
    const float* encoder_outputs = (const float*)d_in[1];
    const void*  mask            = d_in[2];
    const float* W_enc           = (const float*)d_in[3];
    const float* W_dec           = (const float*)d_in[4];
    const float* W_energy        = (const float*)d_in[5];

    float* out_context = (float*)d_out;
    float* out_weights = (float*)d_out + (size_t)BB * ED;

    static bool attr_set = false;
    const int dyn_bytes = NSTAGE * STAGE_FLOATS * 4;   // 4 * 36864 = 147456
    if (!attr_set) {
        cudaFuncSetAttribute(score_mma_kernel,
                             cudaFuncAttributeMaxDynamicSharedMemorySize, dyn_bytes);
        attr_set = true;
    }

    decfeat_kernel<<<dim3(BB, AD / 8), 256>>>(decoder_hidden, W_dec);
    score_mma_kernel<<<dim3(4 * BB, SS / 128), 256, dyn_bytes>>>(
        encoder_outputs, W_enc, W_energy);
    mask_detect_kernel<<<1, 256>>>((const unsigned int*)mask);
    softmax_kernel<<<BB, 256>>>(mask, out_weights);
    context_kernel<<<dim3(BB, ED / 256), 256>>>(encoder_outputs, out_weights, out_context);
}

// round 6
// speedup vs baseline: 2.7089x; 1.0019x over previous
#include <cuda_runtime.h>
#include <math.h>
#include <float.h>
#include <stdint.h>

#define BB 64
#define SS 2048
#define ED 1024
#define AD 512

// Scratch (allocation-free rule: __device__ globals)
__device__ float g_dec_feat[BB * AD];       // [B, AD]
__device__ float g_part[4 * BB * SS];       // [nc][B, S] score partials
__device__ int   g_mask_mode;               // 0=int32, 1=float32, 2=uint8

__device__ __forceinline__ uint32_t smem_u32(const void* p) {
    uint32_t a;
    asm("{ .reg .u64 t; cvta.to.shared.u64 t, %1; cvt.u32.u64 %0, t; }"
        : "=r"(a) : "l"(p));
    return a;
}
__device__ __forceinline__ uint32_t f2tf32(float x) {
    uint32_t r;
    asm("cvt.rna.tf32.f32 %0, %1;" : "=r"(r) : "f"(x));
    return r;
}

// ---------------------------------------------------------------------------
// Kernel 1: dec_feat[b][a] = dot(decoder_hidden[b], W_dec[a])
// ---------------------------------------------------------------------------
__global__ void decfeat_kernel(const float* __restrict__ dh,
                               const float* __restrict__ Wdec) {
    int b = blockIdx.x;
    __shared__ float s_dh[ED];
    for (int i = threadIdx.x; i < ED; i += 256) s_dh[i] = dh[b * ED + i];
    __syncthreads();
    int warp = threadIdx.x >> 5;
    int lane = threadIdx.x & 31;
    int a = blockIdx.y * 8 + warp;
    const float* wr = Wdec + (size_t)a * ED;
    float acc = 0.f;
    #pragma unroll 8
    for (int k = lane; k < ED; k += 32) acc += s_dh[k] * wr[k];
    #pragma unroll
    for (int off = 16; off; off >>= 1) acc += __shfl_down_sync(0xffffffffu, acc, off);
    if (lane == 0) g_dec_feat[b * AD + a] = acc;
}

// ---------------------------------------------------------------------------
// Kernel 2: tf32 mma.sync fused score kernel.
// Per CTA: 128 s-rows x 128 a-cols, K=1024, BK=32, 4-stage cp.async pipeline.
// partial[nc][b,s] = sum_{a in chunk} We[a] * tanh(X.Wenc^T + dec)
// ---------------------------------------------------------------------------
#define BK 32
#define NK (ED / BK)          // 32
#define NSTAGE 4
#define RS 36                 // smem row stride in floats (36 % 32 == 4)
#define STAGE_FLOATS (256 * RS)   // X 128 rows + W 128 rows

__global__ void __launch_bounds__(256, 1)
score_mma_kernel(const float* __restrict__ X,     // [B*S, ED]
                 const float* __restrict__ Wenc,  // [AD, ED]
                 const float* __restrict__ Wen)   // [AD]
{
    extern __shared__ float smem[];
    __shared__ float s_dec[128];
    __shared__ float s_we[128];
    __shared__ float s_red[2][128];

    int tid  = threadIdx.x;
    int wid  = tid >> 5;
    int lane = tid & 31;
    int g    = lane >> 2;
    int tig  = lane & 3;
    int warpm = wid & 3;       // 0..3
    int warpn = wid >> 2;      // 0..1

    int nc = blockIdx.x & 3;
    int b  = blockIdx.x >> 2;
    int s0 = blockIdx.y * 128;

    const float* Xblk = X + (size_t)(b * SS + s0) * ED;
    const float* Wblk = Wenc + (size_t)(nc * 128) * ED;

    for (int i = tid; i < 128; i += 256) {
        s_dec[i] = g_dec_feat[b * AD + nc * 128 + i];
        s_we[i]  = Wen[nc * 128 + i];
    }

    uint32_t sm0 = smem_u32(smem);

    // issue one stage's cp.asyncs: slot p, k-chunk kc
    auto issue_stage = [&](int p, int kc) {
        uint32_t base = sm0 + (uint32_t)(p * STAGE_FLOATS) * 4u;
        int k0 = kc * BK;
        #pragma unroll
        for (int i = 0; i < 8; ++i) {
            int c = tid + i * 256;        // 0..2047
            int row = (c >> 3) & 127;
            int q = c & 7;
            const float* src;
            uint32_t dst;
            if (c < 1024) {
                src = Xblk + (size_t)row * ED + k0 + q * 4;
                dst = base + (uint32_t)(row * RS + q * 4) * 4u;
            } else {
                src = Wblk + (size_t)row * ED + k0 + q * 4;
                dst = base + (uint32_t)((128 + row) * RS + q * 4) * 4u;
            }
            asm volatile("cp.async.cg.shared.global [%0], [%1], 16;"
                         :: "r"(dst), "l"(src));
        }
        asm volatile("cp.async.commit_group;" ::: "memory");
    };

    // prologue: stages 0..NSTAGE-2
    issue_stage(0, 0);
    issue_stage(1, 1);
    issue_stage(2, 2);

    float acc[2][8][4];
    #pragma unroll
    for (int mf = 0; mf < 2; ++mf)
        #pragma unroll
        for (int nf = 0; nf < 8; ++nf)
            #pragma unroll
            for (int r = 0; r < 4; ++r) acc[mf][nf][r] = 0.f;

    for (int kt = 0; kt < NK; ++kt) {
        int p = kt & (NSTAGE - 1);
        asm volatile("cp.async.wait_group %0;" :: "n"(NSTAGE - 2) : "memory");
        __syncthreads();

        const float* xs = smem + p * STAGE_FLOATS;
        const float* ws = xs + 128 * RS;

        #pragma unroll
        for (int ks = 0; ks < 4; ++ks) {
            int kb = ks * 8 + tig;
            uint32_t A[2][4];
            #pragma unroll
            for (int mf = 0; mf < 2; ++mf) {
                int r = warpm * 32 + mf * 16 + g;
                const float* xr = xs + r * RS + kb;
                A[mf][0] = f2tf32(xr[0]);
                A[mf][1] = f2tf32(xr[8 * RS]);
                A[mf][2] = f2tf32(xr[4]);
                A[mf][3] = f2tf32(xr[8 * RS + 4]);
            }
            uint32_t Bf[8][2];
            #pragma unroll
            for (int nf = 0; nf < 8; ++nf) {
                int n = warpn * 64 + nf * 8 + g;
                const float* wr = ws + n * RS + kb;
                Bf[nf][0] = f2tf32(wr[0]);
                Bf[nf][1] = f2tf32(wr[4]);
            }
            #pragma unroll
            for (int mf = 0; mf < 2; ++mf)
                #pragma unroll
                for (int nf = 0; nf < 8; ++nf) {
                    float* c = acc[mf][nf];
                    asm volatile(
                        "mma.sync.aligned.m16n8k8.row.col.f32.tf32.tf32.f32 "
                        "{%0,%1,%2,%3}, {%4,%5,%6,%7}, {%8,%9}, {%0,%1,%2,%3};"
                        : "+f"(c[0]), "+f"(c[1]), "+f"(c[2]), "+f"(c[3])
                        : "r"(A[mf][0]), "r"(A[mf][1]), "r"(A[mf][2]), "r"(A[mf][3]),
                          "r"(Bf[nf][0]), "r"(Bf[nf][1]));
                }
        }
        __syncthreads();
        if (kt + NSTAGE - 1 < NK)
            issue_stage((kt + NSTAGE - 1) & (NSTAGE - 1), kt + NSTAGE - 1);
    }

    // ---- epilogue: tanh + We reduction ----
    #pragma unroll
    for (int mf = 0; mf < 2; ++mf) {
        float sum0 = 0.f, sum1 = 0.f;
        #pragma unroll
        for (int nf = 0; nf < 8; ++nf) {
            int cA = warpn * 64 + nf * 8 + 2 * tig;
            int cB = cA + 1;
            sum0 += s_we[cA] * tanhf(acc[mf][nf][0] + s_dec[cA])
                  + s_we[cB] * tanhf(acc[mf][nf][1] + s_dec[cB]);
            sum1 += s_we[cA] * tanhf(acc[mf][nf][2] + s_dec[cA])
                  + s_we[cB] * tanhf(acc[mf][nf][3] + s_dec[cB]);
        }
        sum0 += __shfl_xor_sync(0xffffffffu, sum0, 1);
        sum0 += __shfl_xor_sync(0xffffffffu, sum0, 2);
        sum1 += __shfl_xor_sync(0xffffffffu, sum1, 1);
        sum1 += __shfl_xor_sync(0xffffffffu, sum1, 2);
        if (tig == 0) {
            int r0 = warpm * 32 + mf * 16 + g;
            s_red[warpn][r0]     = sum0;
            s_red[warpn][r0 + 8] = sum1;
        }
    }
    __syncthreads();
    if (tid < 128)
        g_part[nc * BB * SS + b * SS + s0 + tid] = s_red[0][tid] + s_red[1][tid];
}

// ---------------------------------------------------------------------------
// Kernel 3: mask dtype detect
// ---------------------------------------------------------------------------
__global__ void mask_detect_kernel(const unsigned int* __restrict__ mw) {
    __shared__ int s_not01, s_notf;
    if (threadIdx.x == 0) { s_not01 = 0; s_notf = 0; }
    __syncthreads();
    int not01 = 0, notf = 0;
    for (int i = threadIdx.x; i < 32768; i += blockDim.x) {
        unsigned int w = mw[i];
        if (w > 1u) not01 = 1;
        if (w != 0u && w != 0x3F800000u) notf = 1;
    }
    if (not01) atomicOr(&s_not01, 1);
    if (notf)  atomicOr(&s_notf, 1);
    __syncthreads();
    if (threadIdx.x == 0)
        g_mask_mode = (!s_not01) ? 0 : (!s_notf ? 1 : 2);
}

// ---------------------------------------------------------------------------
// Kernel 4: masked softmax (sums the 4 score partials)
// ---------------------------------------------------------------------------
__global__ void softmax_kernel(const void* __restrict__ mask,
                               float* __restrict__ wout) {
    int b = blockIdx.x;
    int tid = threadIdx.x;
    int mode = g_mask_mode;
    __shared__ float red[256];

    float sv[8];
    float mx = -FLT_MAX;
    #pragma unroll
    for (int i = 0; i < 8; ++i) {
        int s = tid + i * 256;
        int idx = b * SS + s;
        float v = g_part[idx] + g_part[BB * SS + idx]
                + g_part[2 * BB * SS + idx] + g_part[3 * BB * SS + idx];
        bool m;
        if (mode == 0)      m = ((const int*)mask)[idx] != 0;
        else if (mode == 1) m = ((const float*)mask)[idx] != 0.f;
        else                m = ((const unsigned char*)mask)[idx] != 0;
        v = m ? -FLT_MAX : v;
        sv[i] = v;
        mx = fmaxf(mx, v);
    }
    red[tid] = mx; __syncthreads();
    for (int off = 128; off; off >>= 1) {
        if (tid < off) red[tid] = fmaxf(red[tid], red[tid + off]);
        __syncthreads();
    }
    mx = red[0];
    __syncthreads();

    float sum = 0.f;
    #pragma unroll
    for (int i = 0; i < 8; ++i) {
        float e = expf(sv[i] - mx);
        sv[i] = e;
        sum += e;
    }
    red[tid] = sum; __syncthreads();
    for (int off = 128; off; off >>= 1) {
        if (tid < off) red[tid] += red[tid + off];
        __syncthreads();
    }
    float inv = 1.f / red[0];
    #pragma unroll
    for (int i = 0; i < 8; ++i)
        wout[b * SS + tid + i * 256] = sv[i] * inv;
}

// ---------------------------------------------------------------------------
// Kernel 5: context[b,e] = sum_s w[b,s] * enc[b,s,e]
// ---------------------------------------------------------------------------
__global__ void context_kernel(const float* __restrict__ enc,
                               const float* __restrict__ w,
                               float* __restrict__ out) {
    int b = blockIdx.x;
    int e = blockIdx.y * 256 + threadIdx.x;
    const float* ep = enc + (size_t)b * SS * ED + e;
    const float* wp = w + b * SS;
    float acc = 0.f;
    for (int s = 0; s < SS; s += 16) {
        #pragma unroll
        for (int u = 0; u < 16; ++u)
            acc += wp[s + u] * ep[(size_t)(s + u) * ED];
    }
    out[(size_t)b * ED + e] = acc;
}

// ---------------------------------------------------------------------------
extern "C" void kernel_launch(void* const* d_in, const int* in_sizes, int n_in,
                              void* d_out, int out_size) {
    const float* decoder_hidden  = (const float*)d_in[0];
    const float* encoder_outputs = (const float*)d_in[1];
    const void*  mask            = d_in[2];
    const float* W_enc           = (const float*)d_in[3];
    const float* W_dec           = (const float*)d_in[4];
    const float* W_energy        = (const float*)d_in[5];

    float* out_context = (float*)d_out;
    float* out_weights = (float*)d_out + (size_t)BB * ED;

    static bool attr_set = false;
    const int dyn_bytes = NSTAGE * STAGE_FLOATS * 4;   // 4 * 36864 = 147456
    if (!attr_set) {
        cudaFuncSetAttribute(score_mma_kernel,
                             cudaFuncAttributeMaxDynamicSharedMemorySize, dyn_bytes);
        attr_set = true;
    }

    decfeat_kernel<<<dim3(BB, AD / 8), 256>>>(decoder_hidden, W_dec);
    score_mma_kernel<<<dim3(4 * BB, SS / 128), 256, dyn_bytes>>>(
        encoder_outputs, W_enc, W_energy);
    mask_detect_kernel<<<1, 256>>>((const unsigned int*)mask);
    softmax_kernel<<<BB, 256>>>(mask, out_weights);
    context_kernel<<<dim3(BB, ED / 256), 256>>>(encoder_outputs, out_weights, out_context);
}